// round 8
// baseline (speedup 1.0000x reference)
#include <cuda_runtime.h>
#include <cuda_fp16.h>

#define N_NODES 100000
#define N_EDGES 1000000
#define N_GRAPHS 64
#define HD 64
#define EPSV 1e-5f
#define GRID 740
#define CHUNK ((N_NODES + GRID - 1) / GRID)   // 136

// ---------------- scratch (device globals; no allocation allowed) ------------
__device__ __half g_yh[N_NODES * HD];  // GEMM output (fp16, randomly gathered)
__device__ float g_xa[N_NODES * HD];   // ping (fp32 layer outputs)
__device__ float g_xb[N_NODES * HD];   // pong
__device__ int   g_deg[N_NODES];       // re-zeroed every run after use
__device__ float g_dinv[N_NODES];
__device__ int   g_rowptr[N_NODES + 1];
__device__ int   g_cursor[N_NODES];
__device__ int2  g_csr[N_EDGES];       // .x = src node, .y = bits of dinv[src]
__device__ int   g_partial[1024];
__device__ float g_ssum[N_GRAPHS * HD];
__device__ float g_cnt[N_GRAPHS];
__device__ int            g_bar_count;
__device__ volatile int   g_bar_gen;

// ---------------- device-wide barrier (sense-reversing, self-resetting) ------
__device__ __forceinline__ void gbar() {
    __syncthreads();
    if (threadIdx.x == 0) {
        __threadfence();
        int gen = g_bar_gen;
        if (atomicAdd(&g_bar_count, 1) == GRID - 1) {
            g_bar_count = 0;
            __threadfence();
            g_bar_gen = gen + 1;
        } else {
            while (g_bar_gen == gen) { __nanosleep(32); }
        }
        __threadfence();
    }
    __syncthreads();
}

__device__ __forceinline__ float4 h4_to_f4(uint2 u) {
    float2 lo = __half22float2(*(__half2*)&u.x);
    float2 hi = __half22float2(*(__half2*)&u.y);
    return make_float4(lo.x, lo.y, hi.x, hi.y);
}

// ---------------- the whole network in one persistent kernel -----------------
__global__ void __launch_bounds__(256, 5) k_all(
    const float* __restrict__ x, const int* __restrict__ src,
    const int* __restrict__ dst, const int* __restrict__ batch,
    const float* __restrict__ Wc,  const float* __restrict__ bc,
    const float* __restrict__ bn_g, const float* __restrict__ bn_b,
    const float* __restrict__ bn_m, const float* __restrict__ bn_v,
    const float* __restrict__ hW1, const float* __restrict__ hb1,
    const float* __restrict__ hg,  const float* __restrict__ hbe,
    const float* __restrict__ hm,  const float* __restrict__ hv,
    const float* __restrict__ hW2, const float* __restrict__ hb2,
    float* __restrict__ out)
{
    __shared__ float s_xs[64 * 64];   // 16 KB: X tile, K-major, swizzled
    __shared__ float s_w [64 * 64];   // 16 KB: W (k-major rows)
    __shared__ int   s_i [256];       // scan scratch

    int tid  = threadIdx.x;
    int bid  = blockIdx.x;
    int gtid = bid * 256 + tid;

    // ===== P0: degree count + zero pool accumulators =====
    for (int e = gtid; e < N_EDGES; e += GRID * 256) atomicAdd(&g_deg[dst[e]], 1);
    if (gtid < N_GRAPHS * HD) g_ssum[gtid] = 0.f;
    if (gtid < N_GRAPHS)      g_cnt[gtid]  = 0.f;
    gbar();

    // ===== P1: per-block chunk reduce (scan phase A) =====
    int i0 = bid * CHUNK + tid;
    int v = 0;
    if (tid < CHUNK && i0 < N_NODES) v = g_deg[i0];
    s_i[tid] = v;
    __syncthreads();
    for (int off = 1; off < 256; off <<= 1) {
        int t = (tid >= off) ? s_i[tid - off] : 0;
        __syncthreads();
        s_i[tid] += t;
        __syncthreads();
    }
    int incl = s_i[tid];
    if (tid == 0) g_partial[bid] = s_i[255];
    gbar();

    // ===== P2: block offset + rowptr/cursor/dinv, re-zero deg =====
    {
        int s = 0;
        for (int idx = tid; idx < bid; idx += 256) s += g_partial[idx];
        s_i[tid] = s;
        __syncthreads();
        for (int off = 128; off > 0; off >>= 1) {
            if (tid < off) s_i[tid] += s_i[tid + off];
            __syncthreads();
        }
        int offset = s_i[0];
        if (tid < CHUNK && i0 < N_NODES) {
            int ex = offset + incl - v;
            g_rowptr[i0] = ex;
            g_cursor[i0] = ex;
            g_dinv[i0]   = rsqrtf((float)(v + 1));
            g_deg[i0]    = 0;
        }
        if (gtid == 0) g_rowptr[N_NODES] = N_EDGES;
    }
    gbar();

    // ===== P3: scatter edges into CSR =====
    for (int e = gtid; e < N_EDGES; e += GRID * 256) {
        int d = dst[e], s = src[e];
        int p = atomicAdd(&g_cursor[d], 1);
        g_csr[p] = make_int2(s, __float_as_int(g_dinv[s]));
    }
    gbar();

    int lane = tid & 31;
    int warp = tid >> 5;
    int c    = tid & 63;
    int rsub = tid >> 6;
    int q    = lane & 15;

    // ===== 5 GCN layers =====
    for (int L = 0; L < 5; L++) {
        const float* X = (L == 0) ? x : ((L & 1) ? (const float*)g_xa : (const float*)g_xb);
        const float* W = Wc + L * 4096;

        // load W into smem (coalesced; synced by first tile's __syncthreads)
#pragma unroll
        for (int it = 0; it < 16; it++) s_w[it * 256 + tid] = W[it * 256 + tid];

        // ---- GEMM phase: Yh = half(X @ W), 64-row tiles, f32x2 ----
        for (int t = bid; t < (N_NODES + 63) / 64; t += GRID) {
            int rt = t * 64;
            __syncthreads();
#pragma unroll
            for (int it = 0; it < 4; it++) {
                int idx = it * 256 + tid;
                int cq = idx & 15, row = idx >> 4;
                int grow = rt + row;
                float4 x4 = make_float4(0.f, 0.f, 0.f, 0.f);
                if (grow < N_NODES) x4 = *(const float4*)&X[(size_t)grow * 64 + 4 * cq];
                int u = row >> 1, rb = row & 1;
                float vals[4] = {x4.x, x4.y, x4.z, x4.w};
#pragma unroll
                for (int m = 0; m < 4; m++) {
                    int K = 4 * cq + m;
                    int gk = (K + (K >> 2)) & 15;
                    s_xs[K * 64 + 2 * (u ^ gk) + rb] = vals[m];
                }
            }
            __syncthreads();

            unsigned long long acc[8];
#pragma unroll
            for (int j = 0; j < 8; j++) acc[j] = 0ULL;

#pragma unroll
            for (int k = 0; k < 64; k++) {
                int gk = (k + (k >> 2)) & 15;
                float wv = s_w[k * 64 + c];
                unsigned long long wp;
                asm("mov.b64 %0, {%1, %1};" : "=l"(wp) : "f"(wv));
                const float* base = &s_xs[k * 64];
#pragma unroll
                for (int j = 0; j < 8; j++) {
                    float2 x2 = *(const float2*)&base[2 * ((rsub * 8 + j) ^ gk)];
                    unsigned long long xv;
                    asm("mov.b64 %0, {%1, %2};" : "=l"(xv) : "f"(x2.x), "f"(x2.y));
                    asm("fma.rn.f32x2 %0, %1, %2, %0;" : "+l"(acc[j]) : "l"(xv), "l"(wp));
                }
            }
#pragma unroll
            for (int j = 0; j < 8; j++) {
                int row = rt + rsub * 16 + 2 * j;
                float lo, hi;
                asm("mov.b64 {%0, %1}, %2;" : "=f"(lo), "=f"(hi) : "l"(acc[j]));
                if (row < N_NODES)     g_yh[(size_t)row * 64 + c]       = __float2half_rn(lo);
                if (row + 1 < N_NODES) g_yh[(size_t)(row + 1) * 64 + c] = __float2half_rn(hi);
            }
        }
        gbar();

        // ---- AGG phase: gather + bias + ReLU + BN + residual ----
        float*       OUT = (L & 1) ? g_xb : g_xa;
        const float* RES = (L == 0) ? nullptr : X;
        const float* bias = bc + L * 64;
        const float* gam  = bn_g + L * 64;
        const float* bet  = bn_b + L * 64;
        const float* mea  = bn_m + L * 64;
        const float* var  = bn_v + L * 64;

        for (int gw = bid * 8 + warp; gw < (N_NODES + 1) / 2; gw += GRID * 8) {
            int node = gw * 2 + (lane >> 4);
            if (node >= N_NODES) continue;

            int beg = g_rowptr[node], end = g_rowptr[node + 1];
            float4 a = make_float4(0.f, 0.f, 0.f, 0.f);

            int e = beg;
            for (; e + 3 < end; e += 4) {
                int2 c0 = g_csr[e];
                int2 c1 = g_csr[e + 1];
                int2 c2 = g_csr[e + 2];
                int2 c3 = g_csr[e + 3];
                uint2 u0 = ((const uint2*)(g_yh + (size_t)c0.x * 64))[q];
                uint2 u1 = ((const uint2*)(g_yh + (size_t)c1.x * 64))[q];
                uint2 u2 = ((const uint2*)(g_yh + (size_t)c2.x * 64))[q];
                uint2 u3 = ((const uint2*)(g_yh + (size_t)c3.x * 64))[q];
                float4 v0 = h4_to_f4(u0), v1 = h4_to_f4(u1);
                float4 v2 = h4_to_f4(u2), v3 = h4_to_f4(u3);
                float w0 = __int_as_float(c0.y), w1 = __int_as_float(c1.y);
                float w2 = __int_as_float(c2.y), w3 = __int_as_float(c3.y);
                a.x += w0 * v0.x + w1 * v1.x + w2 * v2.x + w3 * v3.x;
                a.y += w0 * v0.y + w1 * v1.y + w2 * v2.y + w3 * v3.y;
                a.z += w0 * v0.z + w1 * v1.z + w2 * v2.z + w3 * v3.z;
                a.w += w0 * v0.w + w1 * v1.w + w2 * v2.w + w3 * v3.w;
            }
            for (; e < end; e++) {
                int2 c0 = g_csr[e];
                uint2 u0 = ((const uint2*)(g_yh + (size_t)c0.x * 64))[q];
                float4 v0 = h4_to_f4(u0);
                float w0 = __int_as_float(c0.y);
                a.x += w0 * v0.x;  a.y += w0 * v0.y;
                a.z += w0 * v0.z;  a.w += w0 * v0.w;
            }

            float  di   = g_dinv[node];
            float4 self = h4_to_f4(((const uint2*)(g_yh + (size_t)node * 64))[q]);
            float4 b    = ((const float4*)bias)[q];
            a.x = di * (a.x + di * self.x) + b.x;
            a.y = di * (a.y + di * self.y) + b.y;
            a.z = di * (a.z + di * self.z) + b.z;
            a.w = di * (a.w + di * self.w) + b.w;
            a.x = fmaxf(a.x, 0.f); a.y = fmaxf(a.y, 0.f);
            a.z = fmaxf(a.z, 0.f); a.w = fmaxf(a.w, 0.f);

            float4 ga = ((const float4*)gam)[q];
            float4 be = ((const float4*)bet)[q];
            float4 mm = ((const float4*)mea)[q];
            float4 vv = ((const float4*)var)[q];
            float4 sc;
            sc.x = ga.x * rsqrtf(vv.x + EPSV);
            sc.y = ga.y * rsqrtf(vv.y + EPSV);
            sc.z = ga.z * rsqrtf(vv.z + EPSV);
            sc.w = ga.w * rsqrtf(vv.w + EPSV);
            a.x = (a.x - mm.x) * sc.x + be.x;
            a.y = (a.y - mm.y) * sc.y + be.y;
            a.z = (a.z - mm.z) * sc.z + be.z;
            a.w = (a.w - mm.w) * sc.w + be.w;

            if (RES) {
                float4 rr = ((const float4*)(RES + (size_t)node * 64))[q];
                a.x += rr.x; a.y += rr.y; a.z += rr.z; a.w += rr.w;
            }
            ((float4*)(OUT + (size_t)node * 64))[q] = a;
        }
        gbar();
    }

    // ===== pool (batch sorted -> run-length accumulate); x5 lives in g_xa =====
    {
        int sub = tid >> 6;                 // 0..3
        int cc  = tid & 63;
        int unit = bid * 4 + sub;
        int start = unit * 128;
        if (start < N_NODES) {
            int endn = min(start + 128, N_NODES);
            float acc = 0.f;
            int run = 0;
            int gcur = batch[start];
            for (int n = start; n < endn; n++) {
                int g = batch[n];
                if (g != gcur) {
                    atomicAdd(&g_ssum[gcur * 64 + cc], acc);
                    if (cc == 0) atomicAdd(&g_cnt[gcur], (float)run);
                    acc = 0.f; run = 0; gcur = g;
                }
                acc += g_xa[(size_t)n * 64 + cc];
                run++;
            }
            atomicAdd(&g_ssum[gcur * 64 + cc], acc);
            if (cc == 0) atomicAdd(&g_cnt[gcur], (float)run);
        }
    }
    gbar();

    // ===== MLP head (block 0, 64 threads) =====
    if (bid == 0 && tid < N_GRAPHS) {
        int g = tid;
        float inv = 1.f / fmaxf(g_cnt[g], 1.f);
        float gv[64];
#pragma unroll
        for (int k = 0; k < 64; k++) gv[k] = g_ssum[g * 64 + k] * inv;
        float o = hb2[0];
        for (int j = 0; j < 32; j++) {
            float s = hb1[j];
#pragma unroll
            for (int k = 0; k < 64; k++) s += gv[k] * hW1[k * 32 + j];
            s = fmaxf(s, 0.f);
            s = (s - hm[j]) * (hg[j] * rsqrtf(hv[j] + EPSV)) + hbe[j];
            o += s * hW2[j];
        }
        out[g] = o;
    }
}

// ---------------- launcher ---------------------------------------------------
extern "C" void kernel_launch(void* const* d_in, const int* in_sizes, int n_in,
                              void* d_out, int out_size) {
    const float* x     = (const float*)d_in[0];
    const int*   ei    = (const int*)  d_in[1];
    const int*   batch = (const int*)  d_in[2];
    const float* Wc    = (const float*)d_in[3];
    const float* bc    = (const float*)d_in[4];
    const float* bn_g  = (const float*)d_in[5];
    const float* bn_b  = (const float*)d_in[6];
    const float* bn_m  = (const float*)d_in[7];
    const float* bn_v  = (const float*)d_in[8];
    const float* hW1   = (const float*)d_in[9];
    const float* hb1   = (const float*)d_in[10];
    const float* hg    = (const float*)d_in[11];
    const float* hbe   = (const float*)d_in[12];
    const float* hm    = (const float*)d_in[13];
    const float* hv    = (const float*)d_in[14];
    const float* hW2   = (const float*)d_in[15];
    const float* hb2   = (const float*)d_in[16];
    float* out = (float*)d_out;

    const int* src = ei;
    const int* dst = ei + N_EDGES;

    k_all<<<GRID, 256>>>(x, src, dst, batch, Wc, bc, bn_g, bn_b, bn_m, bn_v,
                         hW1, hb1, hg, hbe, hm, hv, hW2, hb2, out);
}

// round 9
// speedup vs baseline: 1.2730x; 1.2730x over previous
#include <cuda_runtime.h>
#include <cuda_fp16.h>

#define N_NODES 100000
#define N_EDGES 1000000
#define N_GRAPHS 64
#define HD 64
#define EPSV 1e-5f
#define AGG_GRID 1036   // 7 blocks/SM x 148 SMs: fully resident, grid-stride

// ---------------- scratch (device globals; no allocation allowed) ------------
__device__ __half g_yh[N_NODES * HD];  // GEMM output (fp16, randomly gathered)
__device__ float g_xa[N_NODES * HD];   // ping (fp32 layer outputs)
__device__ float g_xb[N_NODES * HD];   // pong
__device__ int   g_deg[N_NODES];       // re-zeroed every run after use
__device__ float g_dinv[N_NODES];
__device__ int   g_rowptr[N_NODES + 1];
__device__ int   g_cursor[N_NODES];
__device__ int2  g_csr[N_EDGES];       // .x = src node, .y = bits of dinv[src]
__device__ int   g_partial[256];       // scan lookback state (agg+1, 0=not ready)
__device__ float g_ssum[N_GRAPHS * HD];
__device__ float g_cnt[N_GRAPHS];
__device__ int   g_pdone;              // pool blocks done

// ---------------- kernel 0: degree count + zero pool/scan state --------------
__global__ void k_count(const int* __restrict__ dst) {
    int e = blockIdx.x * blockDim.x + threadIdx.x;
    if (e < N_EDGES) atomicAdd(&g_deg[dst[e]], 1);
    if (e < N_GRAPHS * HD) g_ssum[e] = 0.f;
    if (e < N_GRAPHS)      g_cnt[e]  = 0.f;
    if (e < 256)           g_partial[e] = 0;
}

// ---------------- kernel 1: scan + dinv + device barrier + scatter -----------
__global__ void __launch_bounds__(512) k_scan_scatter(const int* __restrict__ src,
                                                      const int* __restrict__ dst) {
    __shared__ int sh[512];
    __shared__ int shp[256];
    int tid = threadIdx.x;
    int bid = blockIdx.x;
    int i = bid * 512 + tid;

    int v = (i < N_NODES) ? g_deg[i] : 0;
    if (i < N_NODES) {
        g_dinv[i] = rsqrtf((float)(v + 1));
        g_deg[i]  = 0;                           // re-zero for next replay
    }

    sh[tid] = v;
    __syncthreads();
    for (int off = 1; off < 512; off <<= 1) {
        int t = (tid >= off) ? sh[tid - off] : 0;
        __syncthreads();
        sh[tid] += t;
        __syncthreads();
    }
    int incl  = sh[tid];
    int total = sh[511];

    if (tid == 0) {                               // publish aggregate
        __threadfence();
        atomicExch(&g_partial[bid], total + 1);
    }

    if (tid < 256) {                              // parallel spin on predecessors
        int p = 0;
        if (tid < bid) {
            do { p = atomicAdd(&g_partial[tid], 0); } while (p == 0);
            p -= 1;
        }
        shp[tid] = p;
    }
    __syncthreads();
    for (int off = 128; off > 0; off >>= 1) {
        if (tid < off) shp[tid] += shp[tid + off];
        __syncthreads();
    }
    int offset = shp[0];

    if (i < N_NODES) {
        int ex = offset + incl - v;
        g_rowptr[i] = ex;
        g_cursor[i] = ex;
    }
    if (bid == 0 && tid == 0) g_rowptr[N_NODES] = N_EDGES;

    // scatter own chunk of edges after cursors for ALL nodes this block covers
    // are ready; need global readiness -> use grid-wide spin on g_partial done
    // count is already satisfied by lookback (all preceding published); but
    // successors' cursors may not be written. Use a simple device barrier:
    __threadfence();
    __syncthreads();
    if (tid == 0) {
        // reuse g_partial[255+...]: separate counters below N=256 region unused
        // (196 blocks). Use atomic counter at g_partial[200..]: simpler: g_pdone.
        atomicAdd(&g_pdone, 1);
        while (atomicAdd(&g_pdone, 0) < (int)gridDim.x) {}
    }
    __syncthreads();

    int stride = gridDim.x * 512;
    for (int e = i; e < N_EDGES; e += stride) {
        int d = dst[e];
        int s = src[e];
        int p = atomicAdd(&g_cursor[d], 1);
        g_csr[p] = make_int2(s, __float_as_int(g_dinv[s]));
    }

    // reset g_pdone for next replay (and for pool kernel which also uses it):
    // last block to finish scatter cannot be identified cheaply; instead reset
    // by thread 0 of block 0 AFTER barrier passed (value == gridDim.x stable,
    // everyone already observed it and moved on only when >= grid).
    if (bid == 0 && tid == 0) {
        // spin until all blocks have passed is unnecessary: value only read
        // against gridDim.x; once all arrived it stays == gridDim.x; safe to
        // reset only when no one will re-check. All blocks re-check only in
        // their own spin loop which exits when >= gridDim.x; a reset to 0
        // could trap a late spinner. Avoid: reset in k_pool_head launch below
        // is not possible (it uses g_pdone too). Use negative epoch trick:
        // leave as is; k_pool_head uses its own logic with modulo.
    }
}

// separate tiny kernel to reset g_pdone between scan_scatter and pool use
__global__ void k_reset() { g_pdone = 0; }

// ---------------- GEMM: Yh = half(X @ W) via packed fma.rn.f32x2 -------------
__global__ void __launch_bounds__(256) k_gemm(const float* __restrict__ Xext, int xsel,
                                              const float* __restrict__ W) {
    __shared__ float xs[64 * 128];
    const float* X = (xsel < 0) ? Xext : (xsel == 0 ? (const float*)g_xa : (const float*)g_xb);

    int tid  = threadIdx.x;
    int c    = tid & 63;
    int rsub = tid >> 6;

    float w[64];
#pragma unroll
    for (int k = 0; k < 64; k++) w[k] = W[k * 64 + c];

    int rt = blockIdx.x * 128;
#pragma unroll
    for (int it = 0; it < 8; it++) {
        int idx = it * 256 + tid;
        int cq  = idx & 15;
        int row = idx >> 4;
        int grow = rt + row;
        float4 x4 = make_float4(0.f, 0.f, 0.f, 0.f);
        if (grow < N_NODES) x4 = *(const float4*)&X[(size_t)grow * 64 + 4 * cq];
        int u  = row >> 1;
        int rb = row & 1;
        float vals[4] = {x4.x, x4.y, x4.z, x4.w};
#pragma unroll
        for (int m = 0; m < 4; m++) {
            int K  = 4 * cq + m;
            int gk = (K + (K >> 2)) & 15;
            xs[K * 128 + 2 * (u ^ gk) + rb] = vals[m];
        }
    }
    __syncthreads();

    unsigned long long acc[16];
#pragma unroll
    for (int j = 0; j < 16; j++) acc[j] = 0ULL;

#pragma unroll
    for (int k = 0; k < 64; k++) {
        const int g = (k + (k >> 2)) & 15;
        unsigned long long wp;
        asm("mov.b64 %0, {%1, %1};" : "=l"(wp) : "f"(w[k]));
        const float* base = &xs[k * 128 + rsub * 32];
#pragma unroll
        for (int j = 0; j < 16; j++) {
            // direct u64 load: LDS.64 destination pair feeds FFMA2, no MOV
            unsigned long long xv = *(const unsigned long long*)&base[2 * (j ^ g)];
            asm("fma.rn.f32x2 %0, %1, %2, %0;" : "+l"(acc[j]) : "l"(xv), "l"(wp));
        }
    }

#pragma unroll
    for (int j = 0; j < 16; j++) {
        int row = rt + rsub * 32 + 2 * j;
        float lo, hi;
        asm("mov.b64 {%0, %1}, %2;" : "=f"(lo), "=f"(hi) : "l"(acc[j]));
        if (row < N_NODES)     g_yh[(size_t)row * 64 + c]       = __float2half_rn(lo);
        if (row + 1 < N_NODES) g_yh[(size_t)(row + 1) * 64 + c] = __float2half_rn(hi);
    }
}

// ---------------- fused aggregation + bias + ReLU + BN + residual ------------
// Fully-resident grid-stride: 1036 blocks x 256 thr, 7 blocks/SM.
// 2 nodes per warp (one per half-warp); lane handles 4 dims (uint2 = 4 halves).
__device__ __forceinline__ float4 h4_to_f4(uint2 u) {
    float2 lo = __half22float2(*(__half2*)&u.x);
    float2 hi = __half22float2(*(__half2*)&u.y);
    return make_float4(lo.x, lo.y, hi.x, hi.y);
}

__global__ void __launch_bounds__(256, 7) k_agg(int res_sel, int out_sel,
                                                const float* __restrict__ bias,
                                                const float* __restrict__ gamma,
                                                const float* __restrict__ beta,
                                                const float* __restrict__ mean,
                                                const float* __restrict__ var) {
    int lane = threadIdx.x & 31;
    int q    = lane & 15;
    int half = lane >> 4;
    int w0i  = (blockIdx.x * 256 + threadIdx.x) >> 5;
    const int NW = AGG_GRID * 8;
    const int NPAIR = N_NODES / 2;      // N_NODES even

    const __half* Yh  = g_yh;
    float*        OUT = out_sel ? g_xb : g_xa;
    const float*  RES = (res_sel < 0) ? nullptr
                                      : (res_sel == 0 ? (const float*)g_xa : (const float*)g_xb);

    // per-thread invariant epilogue params
    float4 b  = ((const float4*)bias)[q];
    float4 ga = ((const float4*)gamma)[q];
    float4 be = ((const float4*)beta)[q];
    float4 mm = ((const float4*)mean)[q];
    float4 vv = ((const float4*)var)[q];
    float4 sc;
    sc.x = ga.x * rsqrtf(vv.x + EPSV);
    sc.y = ga.y * rsqrtf(vv.y + EPSV);
    sc.z = ga.z * rsqrtf(vv.z + EPSV);
    sc.w = ga.w * rsqrtf(vv.w + EPSV);
    // fold: out = (relu(v) - mean)*sc + beta  ->  relu(v)*sc + (beta - mean*sc)
    float4 sh;
    sh.x = be.x - mm.x * sc.x;
    sh.y = be.y - mm.y * sc.y;
    sh.z = be.z - mm.z * sc.z;
    sh.w = be.w - mm.w * sc.w;

    for (int gw = w0i; gw < NPAIR; gw += NW) {
        int node = gw * 2 + half;

        int beg = g_rowptr[node], end = g_rowptr[node + 1];
        float4 a = make_float4(0.f, 0.f, 0.f, 0.f);

        int e = beg;
        for (; e + 3 < end; e += 4) {
            int2 c0 = g_csr[e];
            int2 c1 = g_csr[e + 1];
            int2 c2 = g_csr[e + 2];
            int2 c3 = g_csr[e + 3];
            uint2 u0 = ((const uint2*)(Yh + (size_t)c0.x * 64))[q];
            uint2 u1 = ((const uint2*)(Yh + (size_t)c1.x * 64))[q];
            uint2 u2 = ((const uint2*)(Yh + (size_t)c2.x * 64))[q];
            uint2 u3 = ((const uint2*)(Yh + (size_t)c3.x * 64))[q];
            float4 v0 = h4_to_f4(u0), v1 = h4_to_f4(u1);
            float4 v2 = h4_to_f4(u2), v3 = h4_to_f4(u3);
            float w0 = __int_as_float(c0.y), w1 = __int_as_float(c1.y);
            float w2 = __int_as_float(c2.y), w3 = __int_as_float(c3.y);
            a.x += w0 * v0.x + w1 * v1.x + w2 * v2.x + w3 * v3.x;
            a.y += w0 * v0.y + w1 * v1.y + w2 * v2.y + w3 * v3.y;
            a.z += w0 * v0.z + w1 * v1.z + w2 * v2.z + w3 * v3.z;
            a.w += w0 * v0.w + w1 * v1.w + w2 * v2.w + w3 * v3.w;
        }
        for (; e < end; e++) {
            int2 c0 = g_csr[e];
            uint2 u0 = ((const uint2*)(Yh + (size_t)c0.x * 64))[q];
            float4 v0 = h4_to_f4(u0);
            float w0 = __int_as_float(c0.y);
            a.x += w0 * v0.x;  a.y += w0 * v0.y;
            a.z += w0 * v0.z;  a.w += w0 * v0.w;
        }

        float  di   = g_dinv[node];
        float4 self = h4_to_f4(((const uint2*)(Yh + (size_t)node * 64))[q]);
        a.x = di * (a.x + di * self.x) + b.x;
        a.y = di * (a.y + di * self.y) + b.y;
        a.z = di * (a.z + di * self.z) + b.z;
        a.w = di * (a.w + di * self.w) + b.w;
        a.x = fmaxf(a.x, 0.f) * sc.x + sh.x;
        a.y = fmaxf(a.y, 0.f) * sc.y + sh.y;
        a.z = fmaxf(a.z, 0.f) * sc.z + sh.z;
        a.w = fmaxf(a.w, 0.f) * sc.w + sh.w;

        if (RES) {
            float4 rr = ((const float4*)(RES + (size_t)node * 64))[q];
            a.x += rr.x; a.y += rr.y; a.z += rr.z; a.w += rr.w;
        }
        ((float4*)(OUT + (size_t)node * 64))[q] = a;
    }
}

// ---------------- pooling + MLP head (fused via last-block-done) -------------
__global__ void k_pool_head(const int* __restrict__ batch,
                            const float* __restrict__ hW1, const float* __restrict__ hb1,
                            const float* __restrict__ hg,  const float* __restrict__ hbeta,
                            const float* __restrict__ hm,  const float* __restrict__ hv,
                            const float* __restrict__ hW2, const float* __restrict__ hb2,
                            float* __restrict__ out) {
    const float* X5 = (const float*)g_xa;
    int c = threadIdx.x;
    int start = blockIdx.x * 512;
    if (start < N_NODES) {
        int endn = min(start + 512, N_NODES);
        float acc = 0.f;
        int run = 0;
        int gcur = batch[start];
        for (int n = start; n < endn; n++) {
            int g = batch[n];
            if (g != gcur) {
                atomicAdd(&g_ssum[gcur * 64 + c], acc);
                if (c == 0) atomicAdd(&g_cnt[gcur], (float)run);
                acc = 0.f; run = 0; gcur = g;
            }
            acc += X5[(size_t)n * 64 + c];
            run++;
        }
        atomicAdd(&g_ssum[gcur * 64 + c], acc);
        if (c == 0) atomicAdd(&g_cnt[gcur], (float)run);
    }

    __threadfence();
    __shared__ int lastf;
    if (threadIdx.x == 0) {
        int d = atomicAdd(&g_pdone, 1);
        lastf = (d == (int)gridDim.x - 1);
        if (lastf) g_pdone = 0;                   // reset for next replay
    }
    __syncthreads();
    if (!lastf) return;

    int g = threadIdx.x;                          // 64 threads = 64 graphs
    float inv = 1.f / fmaxf(g_cnt[g], 1.f);
    float gv[64];
#pragma unroll
    for (int k = 0; k < 64; k++) gv[k] = g_ssum[g * 64 + k] * inv;
    float o = hb2[0];
    for (int j = 0; j < 32; j++) {
        float s = hb1[j];
#pragma unroll
        for (int k = 0; k < 64; k++) s += gv[k] * hW1[k * 32 + j];
        s = fmaxf(s, 0.f);
        s = (s - hm[j]) * (hg[j] * rsqrtf(hv[j] + EPSV)) + hbeta[j];
        o += s * hW2[j];
    }
    out[g] = o;
}

// ---------------- launcher ---------------------------------------------------
extern "C" void kernel_launch(void* const* d_in, const int* in_sizes, int n_in,
                              void* d_out, int out_size) {
    const float* x     = (const float*)d_in[0];
    const int*   ei    = (const int*)  d_in[1];
    const int*   batch = (const int*)  d_in[2];
    const float* Wc    = (const float*)d_in[3];
    const float* bc    = (const float*)d_in[4];
    const float* bn_g  = (const float*)d_in[5];
    const float* bn_b  = (const float*)d_in[6];
    const float* bn_m  = (const float*)d_in[7];
    const float* bn_v  = (const float*)d_in[8];
    const float* hW1   = (const float*)d_in[9];
    const float* hb1   = (const float*)d_in[10];
    const float* hg    = (const float*)d_in[11];
    const float* hbe   = (const float*)d_in[12];
    const float* hm    = (const float*)d_in[13];
    const float* hv    = (const float*)d_in[14];
    const float* hW2   = (const float*)d_in[15];
    const float* hb2   = (const float*)d_in[16];
    float* out = (float*)d_out;

    const int* src = ei;
    const int* dst = ei + N_EDGES;

    // --- CSR build ---
    k_count       <<<(N_EDGES + 255) / 256, 256>>>(dst);
    k_scan_scatter<<<(N_NODES + 511) / 512, 512>>>(src, dst);
    k_reset       <<<1, 1>>>();

    // --- 5 GCN layers ---
    const int gemm_grid = (N_NODES + 127) / 128;                // 782

    k_gemm<<<gemm_grid, 256>>>(x, -1, Wc + 0 * 4096);
    k_agg <<<AGG_GRID, 256>>>(-1, 0, bc + 0, bn_g + 0, bn_b + 0, bn_m + 0, bn_v + 0);
    k_gemm<<<gemm_grid, 256>>>(nullptr, 0, Wc + 1 * 4096);
    k_agg <<<AGG_GRID, 256>>>(0, 1, bc + 64, bn_g + 64, bn_b + 64, bn_m + 64, bn_v + 64);
    k_gemm<<<gemm_grid, 256>>>(nullptr, 1, Wc + 2 * 4096);
    k_agg <<<AGG_GRID, 256>>>(1, 0, bc + 128, bn_g + 128, bn_b + 128, bn_m + 128, bn_v + 128);
    k_gemm<<<gemm_grid, 256>>>(nullptr, 0, Wc + 3 * 4096);
    k_agg <<<AGG_GRID, 256>>>(0, 1, bc + 192, bn_g + 192, bn_b + 192, bn_m + 192, bn_v + 192);
    k_gemm<<<gemm_grid, 256>>>(nullptr, 1, Wc + 4 * 4096);
    k_agg <<<AGG_GRID, 256>>>(1, 0, bc + 256, bn_g + 256, bn_b + 256, bn_m + 256, bn_v + 256);

    // --- pool + head (fused) ---
    k_pool_head<<<(N_NODES + 511) / 512, 64>>>(batch, hW1, hb1, hg, hbe, hm, hv, hW2, hb2, out);
}

// round 10
// speedup vs baseline: 1.4147x; 1.1114x over previous
#include <cuda_runtime.h>
#include <cuda_fp16.h>

#define N_NODES 100000
#define N_EDGES 1000000
#define N_GRAPHS 64
#define HD 64
#define EPSV 1e-5f

// ---------------- scratch (device globals; no allocation allowed) ------------
__device__ __half g_yh[N_NODES * HD];  // GEMM output (fp16, randomly gathered)
__device__ float g_xa[N_NODES * HD];   // ping (fp32 layer outputs)
__device__ float g_xb[N_NODES * HD];   // pong
__device__ int   g_deg[N_NODES];       // re-zeroed every run after use
__device__ float g_dinv[N_NODES];
__device__ int   g_rowptr[N_NODES + 1];
__device__ int   g_cursor[N_NODES];
__device__ int2  g_csr[N_EDGES];       // .x = src node, .y = bits of dinv[src]
__device__ int   g_partial[256];       // scan lookback state (agg+1, 0=not ready)
__device__ float g_ssum[N_GRAPHS * HD];
__device__ float g_cnt[N_GRAPHS];
__device__ int   g_sync1;              // device-wide barrier arrive count
__device__ int   g_sync2;              // device-wide barrier pass count
__device__ int   g_pdone;              // pool blocks done

// ---------------- kernel 0: degree count + zero pool/scan state --------------
__global__ void k_count(const int* __restrict__ dst) {
    int e = blockIdx.x * blockDim.x + threadIdx.x;
    if (e < N_EDGES) atomicAdd(&g_deg[dst[e]], 1);
    if (e < N_GRAPHS * HD) g_ssum[e] = 0.f;
    if (e < N_GRAPHS)      g_cnt[e]  = 0.f;
    if (e < 256)           g_partial[e] = 0;
}

// ---------------- kernel 1: scan + dinv + device barrier + scatter -----------
__global__ void __launch_bounds__(512) k_scan_scatter(const int* __restrict__ src,
                                                      const int* __restrict__ dst) {
    __shared__ int sh[512];
    __shared__ int shp[256];
    int tid = threadIdx.x;
    int bid = blockIdx.x;
    int i = bid * 512 + tid;

    int v = (i < N_NODES) ? g_deg[i] : 0;
    if (i < N_NODES) {
        g_dinv[i] = rsqrtf((float)(v + 1));
        g_deg[i]  = 0;                           // re-zero for next replay
    }

    sh[tid] = v;
    __syncthreads();
    for (int off = 1; off < 512; off <<= 1) {
        int t = (tid >= off) ? sh[tid - off] : 0;
        __syncthreads();
        sh[tid] += t;
        __syncthreads();
    }
    int incl  = sh[tid];
    int total = sh[511];

    if (tid == 0) {                               // publish aggregate
        __threadfence();
        atomicExch(&g_partial[bid], total + 1);
    }

    if (tid < 256) {                              // parallel spin on predecessors
        int p = 0;
        if (tid < bid) {
            do { p = atomicAdd(&g_partial[tid], 0); } while (p == 0);
            p -= 1;
        }
        shp[tid] = p;
    }
    __syncthreads();
    for (int off = 128; off > 0; off >>= 1) {
        if (tid < off) shp[tid] += shp[tid + off];
        __syncthreads();
    }
    int offset = shp[0];

    if (i < N_NODES) {
        int ex = offset + incl - v;
        g_rowptr[i] = ex;
        g_cursor[i] = ex;
    }
    if (bid == 0 && tid == 0) g_rowptr[N_NODES] = N_EDGES;

    // ---- device-wide barrier (self-resetting) ----
    __threadfence();
    __syncthreads();
    if (tid == 0) {
        atomicAdd(&g_sync1, 1);
        while (atomicAdd(&g_sync1, 0) < (int)gridDim.x) {}
        int p = atomicAdd(&g_sync2, 1);
        if (p == (int)gridDim.x - 1) {            // last to pass: everyone is out
            g_sync1 = 0;
            g_sync2 = 0;
            __threadfence();
        }
    }
    __syncthreads();

    // ---- phase 2: scatter edges into CSR ----
    int stride = gridDim.x * 512;
    for (int e = i; e < N_EDGES; e += stride) {
        int d = dst[e];
        int s = src[e];
        int p = atomicAdd(&g_cursor[d], 1);
        g_csr[p] = make_int2(s, __float_as_int(g_dinv[s]));
    }
}

// ---------------- GEMM v3: outer-product f32x2, Yh = half(X @ W) -------------
// 256 thr, 128 rows/block. Thread = 4 row-pairs x 4 cols (32 f32x2 accs).
// Per k: 4 broadcast LDS.64 (x) + 4 LDS.32 (w) + 4 packs -> 16 FFMA2.
// Swizzle XOR decomposed: rp0 aligned to 4 => 4 precomputed bases (gk>>2),
// compile-time offsets (gk&3). Zero per-k address ALU.
__global__ void __launch_bounds__(256) k_gemm(const float* __restrict__ Xext, int xsel,
                                              const float* __restrict__ W) {
    __shared__ float xs[64 * 128];   // 32KB: [k][2*rp + b], swizzled
    __shared__ float wt[64 * 64];    // 16KB: W copy, row-major [k][c]
    const float* X = (xsel < 0) ? Xext : (xsel == 0 ? (const float*)g_xa : (const float*)g_xb);

    int tid  = threadIdx.x;
    int lane = tid & 31;
    int wid  = tid >> 5;          // 0..7
    int cg   = lane & 15;         // col group: cols cg*4 .. cg*4+3
    int rh   = lane >> 4;         // 0/1
    int rg   = wid * 2 + rh;      // 0..15 -> rows rg*8 .. rg*8+7
    int rp0  = rg * 4;            // first row-pair (aligned to 4)

    // stage W (4096 floats)
#pragma unroll
    for (int it = 0; it < 16; it++) wt[it * 256 + tid] = W[it * 256 + tid];

    int rt = blockIdx.x * 128;
    // stage X tile K-major with swizzle (identical to proven R7 layout)
#pragma unroll
    for (int it = 0; it < 8; it++) {
        int idx = it * 256 + tid;
        int cq  = idx & 15;
        int row = idx >> 4;
        int grow = rt + row;
        float4 x4 = make_float4(0.f, 0.f, 0.f, 0.f);
        if (grow < N_NODES) x4 = *(const float4*)&X[(size_t)grow * 64 + 4 * cq];
        int u  = row >> 1;
        int rb = row & 1;
        float vals[4] = {x4.x, x4.y, x4.z, x4.w};
#pragma unroll
        for (int m = 0; m < 4; m++) {
            int K  = 4 * cq + m;
            int gk = (K + (K >> 2)) & 15;
            xs[K * 128 + 2 * (u ^ gk) + rb] = vals[m];
        }
    }
    __syncthreads();

    // 4 precomputed x bases for gk&~3 in {0,4,8,12}
    const float* xb0 = &xs[2 * (rp0 ^ 0)];
    const float* xb1 = &xs[2 * (rp0 ^ 4)];
    const float* xb2 = &xs[2 * (rp0 ^ 8)];
    const float* xb3 = &xs[2 * (rp0 ^ 12)];
    const float* wb  = &wt[cg * 4];

    unsigned long long acc[4][4];
#pragma unroll
    for (int j = 0; j < 4; j++)
#pragma unroll
        for (int cc = 0; cc < 4; cc++) acc[j][cc] = 0ULL;

#pragma unroll
    for (int k = 0; k < 64; k++) {
        const int gk  = (k + (k >> 2)) & 15;   // compile-time per k
        const int ghi = gk >> 2;
        const int glo = gk & 3;
        const float* xbase = (ghi == 0) ? xb0 : (ghi == 1) ? xb1 : (ghi == 2) ? xb2 : xb3;

        unsigned long long x2[4];
#pragma unroll
        for (int j = 0; j < 4; j++)
            x2[j] = *(const unsigned long long*)&xbase[k * 128 + 2 * (j ^ glo)];

        unsigned long long wd[4];
#pragma unroll
        for (int cc = 0; cc < 4; cc++) {
            float wv = wb[k * 64 + cc];
            asm("mov.b64 %0, {%1, %1};" : "=l"(wd[cc]) : "f"(wv));
        }

#pragma unroll
        for (int j = 0; j < 4; j++)
#pragma unroll
            for (int cc = 0; cc < 4; cc++)
                asm("fma.rn.f32x2 %0, %1, %2, %0;"
                    : "+l"(acc[j][cc]) : "l"(x2[j]), "l"(wd[cc]));
    }

    // epilogue: rows rt + rg*8 + 2j (+1), cols cg*4 .. +3, fp16 out
#pragma unroll
    for (int j = 0; j < 4; j++) {
        int row = rt + rg * 8 + 2 * j;
        float lo0, hi0, lo1, hi1, lo2, hi2, lo3, hi3;
        asm("mov.b64 {%0,%1}, %2;" : "=f"(lo0), "=f"(hi0) : "l"(acc[j][0]));
        asm("mov.b64 {%0,%1}, %2;" : "=f"(lo1), "=f"(hi1) : "l"(acc[j][1]));
        asm("mov.b64 {%0,%1}, %2;" : "=f"(lo2), "=f"(hi2) : "l"(acc[j][2]));
        asm("mov.b64 {%0,%1}, %2;" : "=f"(lo3), "=f"(hi3) : "l"(acc[j][3]));
        if (row < N_NODES) {
            __half2* p = (__half2*)&g_yh[(size_t)row * 64 + cg * 4];
            p[0] = __floats2half2_rn(lo0, lo1);
            p[1] = __floats2half2_rn(lo2, lo3);
        }
        if (row + 1 < N_NODES) {
            __half2* p = (__half2*)&g_yh[(size_t)(row + 1) * 64 + cg * 4];
            p[0] = __floats2half2_rn(hi0, hi1);
            p[1] = __floats2half2_rn(hi2, hi3);
        }
    }
}

// ---------------- fused aggregation + bias + ReLU + BN + residual ------------
// (proven R7 version) 2 nodes per warp; lane handles 4 dims (uint2 = 4 halves).
__device__ __forceinline__ float4 h4_to_f4(uint2 u) {
    float2 lo = __half22float2(*(__half2*)&u.x);
    float2 hi = __half22float2(*(__half2*)&u.y);
    return make_float4(lo.x, lo.y, hi.x, hi.y);
}

__global__ void __launch_bounds__(256) k_agg(int res_sel, int out_sel,
                                             const float* __restrict__ bias,
                                             const float* __restrict__ gamma,
                                             const float* __restrict__ beta,
                                             const float* __restrict__ mean,
                                             const float* __restrict__ var) {
    int gw   = (blockIdx.x * blockDim.x + threadIdx.x) >> 5;
    int lane = threadIdx.x & 31;
    int node = gw * 2 + (lane >> 4);
    if (node >= N_NODES) return;
    int q = lane & 15;

    const __half* Yh  = g_yh;
    float*        OUT = out_sel ? g_xb : g_xa;
    const float*  RES = (res_sel < 0) ? nullptr
                                      : (res_sel == 0 ? (const float*)g_xa : (const float*)g_xb);

    int beg = g_rowptr[node], end = g_rowptr[node + 1];
    float4 a = make_float4(0.f, 0.f, 0.f, 0.f);

    int e = beg;
    for (; e + 3 < end; e += 4) {
        int2 c0 = g_csr[e];
        int2 c1 = g_csr[e + 1];
        int2 c2 = g_csr[e + 2];
        int2 c3 = g_csr[e + 3];
        uint2 u0 = ((const uint2*)(Yh + (size_t)c0.x * 64))[q];
        uint2 u1 = ((const uint2*)(Yh + (size_t)c1.x * 64))[q];
        uint2 u2 = ((const uint2*)(Yh + (size_t)c2.x * 64))[q];
        uint2 u3 = ((const uint2*)(Yh + (size_t)c3.x * 64))[q];
        float4 v0 = h4_to_f4(u0), v1 = h4_to_f4(u1);
        float4 v2 = h4_to_f4(u2), v3 = h4_to_f4(u3);
        float w0 = __int_as_float(c0.y), w1 = __int_as_float(c1.y);
        float w2 = __int_as_float(c2.y), w3 = __int_as_float(c3.y);
        a.x += w0 * v0.x + w1 * v1.x + w2 * v2.x + w3 * v3.x;
        a.y += w0 * v0.y + w1 * v1.y + w2 * v2.y + w3 * v3.y;
        a.z += w0 * v0.z + w1 * v1.z + w2 * v2.z + w3 * v3.z;
        a.w += w0 * v0.w + w1 * v1.w + w2 * v2.w + w3 * v3.w;
    }
    for (; e < end; e++) {
        int2 c0 = g_csr[e];
        uint2 u0 = ((const uint2*)(Yh + (size_t)c0.x * 64))[q];
        float4 v0 = h4_to_f4(u0);
        float w0 = __int_as_float(c0.y);
        a.x += w0 * v0.x;  a.y += w0 * v0.y;
        a.z += w0 * v0.z;  a.w += w0 * v0.w;
    }

    float  di   = g_dinv[node];
    float4 self = h4_to_f4(((const uint2*)(Yh + (size_t)node * 64))[q]);
    float4 b    = ((const float4*)bias)[q];
    a.x = di * (a.x + di * self.x) + b.x;
    a.y = di * (a.y + di * self.y) + b.y;
    a.z = di * (a.z + di * self.z) + b.z;
    a.w = di * (a.w + di * self.w) + b.w;
    a.x = fmaxf(a.x, 0.f); a.y = fmaxf(a.y, 0.f);
    a.z = fmaxf(a.z, 0.f); a.w = fmaxf(a.w, 0.f);

    float4 ga = ((const float4*)gamma)[q];
    float4 be = ((const float4*)beta)[q];
    float4 mm = ((const float4*)mean)[q];
    float4 vv = ((const float4*)var)[q];
    float4 sc;
    sc.x = ga.x * rsqrtf(vv.x + EPSV);
    sc.y = ga.y * rsqrtf(vv.y + EPSV);
    sc.z = ga.z * rsqrtf(vv.z + EPSV);
    sc.w = ga.w * rsqrtf(vv.w + EPSV);
    a.x = (a.x - mm.x) * sc.x + be.x;
    a.y = (a.y - mm.y) * sc.y + be.y;
    a.z = (a.z - mm.z) * sc.z + be.z;
    a.w = (a.w - mm.w) * sc.w + be.w;

    if (RES) {
        float4 rr = ((const float4*)(RES + (size_t)node * 64))[q];
        a.x += rr.x; a.y += rr.y; a.z += rr.z; a.w += rr.w;
    }
    ((float4*)(OUT + (size_t)node * 64))[q] = a;
}

// ---------------- pooling + MLP head (fused via last-block-done) -------------
__global__ void k_pool_head(const int* __restrict__ batch,
                            const float* __restrict__ hW1, const float* __restrict__ hb1,
                            const float* __restrict__ hg,  const float* __restrict__ hbeta,
                            const float* __restrict__ hm,  const float* __restrict__ hv,
                            const float* __restrict__ hW2, const float* __restrict__ hb2,
                            float* __restrict__ out) {
    const float* X5 = (const float*)g_xa;
    int c = threadIdx.x;
    int start = blockIdx.x * 512;
    if (start < N_NODES) {
        int endn = min(start + 512, N_NODES);
        float acc = 0.f;
        int run = 0;
        int gcur = batch[start];
        for (int n = start; n < endn; n++) {
            int g = batch[n];
            if (g != gcur) {
                atomicAdd(&g_ssum[gcur * 64 + c], acc);
                if (c == 0) atomicAdd(&g_cnt[gcur], (float)run);
                acc = 0.f; run = 0; gcur = g;
            }
            acc += X5[(size_t)n * 64 + c];
            run++;
        }
        atomicAdd(&g_ssum[gcur * 64 + c], acc);
        if (c == 0) atomicAdd(&g_cnt[gcur], (float)run);
    }

    __threadfence();
    __shared__ int lastf;
    if (threadIdx.x == 0) {
        int d = atomicAdd(&g_pdone, 1);
        lastf = (d == (int)gridDim.x - 1);
        if (lastf) g_pdone = 0;                   // reset for next replay
    }
    __syncthreads();
    if (!lastf) return;

    int g = threadIdx.x;                          // 64 threads = 64 graphs
    float inv = 1.f / fmaxf(g_cnt[g], 1.f);
    float gv[64];
#pragma unroll
    for (int k = 0; k < 64; k++) gv[k] = g_ssum[g * 64 + k] * inv;
    float o = hb2[0];
    for (int j = 0; j < 32; j++) {
        float s = hb1[j];
#pragma unroll
        for (int k = 0; k < 64; k++) s += gv[k] * hW1[k * 32 + j];
        s = fmaxf(s, 0.f);
        s = (s - hm[j]) * (hg[j] * rsqrtf(hv[j] + EPSV)) + hbeta[j];
        o += s * hW2[j];
    }
    out[g] = o;
}

// ---------------- launcher ---------------------------------------------------
extern "C" void kernel_launch(void* const* d_in, const int* in_sizes, int n_in,
                              void* d_out, int out_size) {
    const float* x     = (const float*)d_in[0];
    const int*   ei    = (const int*)  d_in[1];
    const int*   batch = (const int*)  d_in[2];
    const float* Wc    = (const float*)d_in[3];
    const float* bc    = (const float*)d_in[4];
    const float* bn_g  = (const float*)d_in[5];
    const float* bn_b  = (const float*)d_in[6];
    const float* bn_m  = (const float*)d_in[7];
    const float* bn_v  = (const float*)d_in[8];
    const float* hW1   = (const float*)d_in[9];
    const float* hb1   = (const float*)d_in[10];
    const float* hg    = (const float*)d_in[11];
    const float* hbe   = (const float*)d_in[12];
    const float* hm    = (const float*)d_in[13];
    const float* hv    = (const float*)d_in[14];
    const float* hW2   = (const float*)d_in[15];
    const float* hb2   = (const float*)d_in[16];
    float* out = (float*)d_out;

    const int* src = ei;
    const int* dst = ei + N_EDGES;

    // --- CSR build: 2 kernels ---
    k_count       <<<(N_EDGES + 255) / 256, 256>>>(dst);
    k_scan_scatter<<<(N_NODES + 511) / 512, 512>>>(src, dst);

    // --- 5 GCN layers ---
    const int gemm_grid = (N_NODES + 127) / 128;                // 782
    const int agg_grid  = ((N_NODES + 1) / 2 * 32 + 255) / 256; // 2 nodes/warp

    k_gemm<<<gemm_grid, 256>>>(x, -1, Wc + 0 * 4096);
    k_agg <<<agg_grid, 256>>>(-1, 0, bc + 0, bn_g + 0, bn_b + 0, bn_m + 0, bn_v + 0);
    k_gemm<<<gemm_grid, 256>>>(nullptr, 0, Wc + 1 * 4096);
    k_agg <<<agg_grid, 256>>>(0, 1, bc + 64, bn_g + 64, bn_b + 64, bn_m + 64, bn_v + 64);
    k_gemm<<<gemm_grid, 256>>>(nullptr, 1, Wc + 2 * 4096);
    k_agg <<<agg_grid, 256>>>(1, 0, bc + 128, bn_g + 128, bn_b + 128, bn_m + 128, bn_v + 128);
    k_gemm<<<gemm_grid, 256>>>(nullptr, 0, Wc + 3 * 4096);
    k_agg <<<agg_grid, 256>>>(0, 1, bc + 192, bn_g + 192, bn_b + 192, bn_m + 192, bn_v + 192);
    k_gemm<<<gemm_grid, 256>>>(nullptr, 1, Wc + 4 * 4096);
    k_agg <<<agg_grid, 256>>>(1, 0, bc + 256, bn_g + 256, bn_b + 256, bn_m + 256, bn_v + 256);

    // --- pool + head (fused) ---
    k_pool_head<<<(N_NODES + 511) / 512, 64>>>(batch, hW1, hb1, hg, hbe, hm, hv, hW2, hb2, out);
}

// round 13
// speedup vs baseline: 1.4732x; 1.0414x over previous
#include <cuda_runtime.h>
#include <cuda_fp16.h>

#define N_NODES 100000
#define N_EDGES 1000000
#define N_GRAPHS 64
#define HD 64
#define EPSV 1e-5f
#define AGG_GRID 1036   // 7 blocks/SM x 148 SMs, fully resident grid-stride

// ---------------- scratch (device globals; no allocation allowed) ------------
__device__ __half g_yh[N_NODES * HD];  // GEMM output (fp16, randomly gathered)
__device__ float g_xa[N_NODES * HD];   // ping (fp32 layer outputs)
__device__ float g_xb[N_NODES * HD];   // pong
__device__ int   g_deg[N_NODES];       // re-zeroed every run after use
__device__ float g_dinv[N_NODES];
__device__ int   g_rowptr[N_NODES + 1];
__device__ int   g_cursor[N_NODES];
__device__ int2  g_csr[N_EDGES];       // .x = src byte offset (src*128), .y = dinv bits
__device__ int   g_partial[256];       // scan lookback state (agg+1, 0=not ready)
__device__ float g_ssum[N_GRAPHS * HD];
__device__ float g_cnt[N_GRAPHS];
__device__ int   g_sync1;              // device-wide barrier arrive count
__device__ int   g_sync2;              // device-wide barrier pass count
__device__ int   g_pdone;              // pool blocks done

// ---------------- kernel 0: degree count + zero pool/scan state --------------
__global__ void k_count(const int* __restrict__ dst) {
    int e = blockIdx.x * blockDim.x + threadIdx.x;
    if (e < N_EDGES) atomicAdd(&g_deg[dst[e]], 1);
    if (e < N_GRAPHS * HD) g_ssum[e] = 0.f;
    if (e < N_GRAPHS)      g_cnt[e]  = 0.f;
    if (e < 256)           g_partial[e] = 0;
}

// ---------------- kernel 1: scan + dinv + device barrier + scatter -----------
__global__ void __launch_bounds__(512) k_scan_scatter(const int* __restrict__ src,
                                                      const int* __restrict__ dst) {
    __shared__ int sh[512];
    __shared__ int shp[256];
    int tid = threadIdx.x;
    int bid = blockIdx.x;
    int i = bid * 512 + tid;

    int v = (i < N_NODES) ? g_deg[i] : 0;
    if (i < N_NODES) {
        g_dinv[i] = rsqrtf((float)(v + 1));
        g_deg[i]  = 0;                           // re-zero for next replay
    }

    sh[tid] = v;
    __syncthreads();
    for (int off = 1; off < 512; off <<= 1) {
        int t = (tid >= off) ? sh[tid - off] : 0;
        __syncthreads();
        sh[tid] += t;
        __syncthreads();
    }
    int incl  = sh[tid];
    int total = sh[511];

    if (tid == 0) {                               // publish aggregate
        __threadfence();
        atomicExch(&g_partial[bid], total + 1);
    }

    if (tid < 256) {                              // parallel spin on predecessors
        int p = 0;
        if (tid < bid) {
            do { p = atomicAdd(&g_partial[tid], 0); } while (p == 0);
            p -= 1;
        }
        shp[tid] = p;
    }
    __syncthreads();
    for (int off = 128; off > 0; off >>= 1) {
        if (tid < off) shp[tid] += shp[tid + off];
        __syncthreads();
    }
    int offset = shp[0];

    if (i < N_NODES) {
        int ex = offset + incl - v;
        g_rowptr[i] = ex;
        g_cursor[i] = ex;
    }
    if (bid == 0 && tid == 0) g_rowptr[N_NODES] = N_EDGES;

    // ---- device-wide barrier (self-resetting) ----
    __threadfence();
    __syncthreads();
    if (tid == 0) {
        atomicAdd(&g_sync1, 1);
        while (atomicAdd(&g_sync1, 0) < (int)gridDim.x) {}
        int p = atomicAdd(&g_sync2, 1);
        if (p == (int)gridDim.x - 1) {            // last to pass: everyone is out
            g_sync1 = 0;
            g_sync2 = 0;
            __threadfence();
        }
    }
    __syncthreads();

    // ---- phase 2: scatter edges into CSR (payload = byte offset of src row) --
    int stride = gridDim.x * 512;
    for (int e = i; e < N_EDGES; e += stride) {
        int d = dst[e];
        int s = src[e];
        int p = atomicAdd(&g_cursor[d], 1);
        g_csr[p] = make_int2(s << 7, __float_as_int(g_dinv[s]));
    }
}

// ---------------- GEMM v3: outer-product f32x2, Yh = half(X @ W) -------------
// (proven R10 version, unchanged)
__global__ void __launch_bounds__(256) k_gemm(const float* __restrict__ Xext, int xsel,
                                              const float* __restrict__ W) {
    __shared__ float xs[64 * 128];   // 32KB: [k][2*rp + b], swizzled
    __shared__ float wt[64 * 64];    // 16KB: W copy, row-major [k][c]
    const float* X = (xsel < 0) ? Xext : (xsel == 0 ? (const float*)g_xa : (const float*)g_xb);

    int tid  = threadIdx.x;
    int lane = tid & 31;
    int wid  = tid >> 5;          // 0..7
    int cg   = lane & 15;         // col group: cols cg*4 .. cg*4+3
    int rh   = lane >> 4;         // 0/1
    int rg   = wid * 2 + rh;      // 0..15 -> rows rg*8 .. rg*8+7
    int rp0  = rg * 4;            // first row-pair (aligned to 4)

#pragma unroll
    for (int it = 0; it < 16; it++) wt[it * 256 + tid] = W[it * 256 + tid];

    int rt = blockIdx.x * 128;
#pragma unroll
    for (int it = 0; it < 8; it++) {
        int idx = it * 256 + tid;
        int cq  = idx & 15;
        int row = idx >> 4;
        int grow = rt + row;
        float4 x4 = make_float4(0.f, 0.f, 0.f, 0.f);
        if (grow < N_NODES) x4 = *(const float4*)&X[(size_t)grow * 64 + 4 * cq];
        int u  = row >> 1;
        int rb = row & 1;
        float vals[4] = {x4.x, x4.y, x4.z, x4.w};
#pragma unroll
        for (int m = 0; m < 4; m++) {
            int K  = 4 * cq + m;
            int gk = (K + (K >> 2)) & 15;
            xs[K * 128 + 2 * (u ^ gk) + rb] = vals[m];
        }
    }
    __syncthreads();

    const float* xb0 = &xs[2 * (rp0 ^ 0)];
    const float* xb1 = &xs[2 * (rp0 ^ 4)];
    const float* xb2 = &xs[2 * (rp0 ^ 8)];
    const float* xb3 = &xs[2 * (rp0 ^ 12)];
    const float* wb  = &wt[cg * 4];

    unsigned long long acc[4][4];
#pragma unroll
    for (int j = 0; j < 4; j++)
#pragma unroll
        for (int cc = 0; cc < 4; cc++) acc[j][cc] = 0ULL;

#pragma unroll
    for (int k = 0; k < 64; k++) {
        const int gk  = (k + (k >> 2)) & 15;
        const int ghi = gk >> 2;
        const int glo = gk & 3;
        const float* xbase = (ghi == 0) ? xb0 : (ghi == 1) ? xb1 : (ghi == 2) ? xb2 : xb3;

        unsigned long long x2[4];
#pragma unroll
        for (int j = 0; j < 4; j++)
            x2[j] = *(const unsigned long long*)&xbase[k * 128 + 2 * (j ^ glo)];

        unsigned long long wd[4];
#pragma unroll
        for (int cc = 0; cc < 4; cc++) {
            float wv = wb[k * 64 + cc];
            asm("mov.b64 %0, {%1, %1};" : "=l"(wd[cc]) : "f"(wv));
        }

#pragma unroll
        for (int j = 0; j < 4; j++)
#pragma unroll
            for (int cc = 0; cc < 4; cc++)
                asm("fma.rn.f32x2 %0, %1, %2, %0;"
                    : "+l"(acc[j][cc]) : "l"(x2[j]), "l"(wd[cc]));
    }

#pragma unroll
    for (int j = 0; j < 4; j++) {
        int row = rt + rg * 8 + 2 * j;
        float lo0, hi0, lo1, hi1, lo2, hi2, lo3, hi3;
        asm("mov.b64 {%0,%1}, %2;" : "=f"(lo0), "=f"(hi0) : "l"(acc[j][0]));
        asm("mov.b64 {%0,%1}, %2;" : "=f"(lo1), "=f"(hi1) : "l"(acc[j][1]));
        asm("mov.b64 {%0,%1}, %2;" : "=f"(lo2), "=f"(hi2) : "l"(acc[j][2]));
        asm("mov.b64 {%0,%1}, %2;" : "=f"(lo3), "=f"(hi3) : "l"(acc[j][3]));
        if (row < N_NODES) {
            __half2* p = (__half2*)&g_yh[(size_t)row * 64 + cg * 4];
            p[0] = __floats2half2_rn(lo0, lo1);
            p[1] = __floats2half2_rn(lo2, lo3);
        }
        if (row + 1 < N_NODES) {
            __half2* p = (__half2*)&g_yh[(size_t)(row + 1) * 64 + cg * 4];
            p[0] = __floats2half2_rn(hi0, hi1);
            p[1] = __floats2half2_rn(hi2, hi3);
        }
    }
}

// ---------------- fused aggregation + bias + ReLU + BN + residual ------------
// v2: byte-offset gathers (no IMAD per edge), fully-resident grid-stride,
// folded BN epilogue. 2 nodes per warp; lane handles 4 dims.
__device__ __forceinline__ float4 h4_to_f4(uint2 u) {
    float2 lo = __half22float2(*(__half2*)&u.x);
    float2 hi = __half22float2(*(__half2*)&u.y);
    return make_float4(lo.x, lo.y, hi.x, hi.y);
}

__global__ void __launch_bounds__(256, 7) k_agg(int res_sel, int out_sel,
                                                const float* __restrict__ bias,
                                                const float* __restrict__ gamma,
                                                const float* __restrict__ beta,
                                                const float* __restrict__ mean,
                                                const float* __restrict__ var) {
    int lane = threadIdx.x & 31;
    int q    = lane & 15;
    int half = lane >> 4;
    int w0i  = (blockIdx.x * 256 + threadIdx.x) >> 5;
    const int NW = AGG_GRID * 8;        // warps in grid
    const int NPAIR = N_NODES / 2;

    const char*   Yq  = (const char*)g_yh + q * 8;   // lane's 8-byte slot
    float*        OUT = out_sel ? g_xb : g_xa;
    const float*  RES = (res_sel < 0) ? nullptr
                                      : (res_sel == 0 ? (const float*)g_xa : (const float*)g_xb);

    // per-thread invariant epilogue params (folded BN)
    float4 b  = ((const float4*)bias)[q];
    float4 ga = ((const float4*)gamma)[q];
    float4 be = ((const float4*)beta)[q];
    float4 mm = ((const float4*)mean)[q];
    float4 vv = ((const float4*)var)[q];
    float4 sc;
    sc.x = ga.x * rsqrtf(vv.x + EPSV);
    sc.y = ga.y * rsqrtf(vv.y + EPSV);
    sc.z = ga.z * rsqrtf(vv.z + EPSV);
    sc.w = ga.w * rsqrtf(vv.w + EPSV);
    float4 shf;
    shf.x = be.x - mm.x * sc.x;
    shf.y = be.y - mm.y * sc.y;
    shf.z = be.z - mm.z * sc.z;
    shf.w = be.w - mm.w * sc.w;

    for (int gw = w0i; gw < NPAIR; gw += NW) {
        int node = gw * 2 + half;

        int beg = g_rowptr[node], end = g_rowptr[node + 1];
        float4 a = make_float4(0.f, 0.f, 0.f, 0.f);

        int e = beg;
        for (; e + 3 < end; e += 4) {
            int2 c0 = g_csr[e];
            int2 c1 = g_csr[e + 1];
            int2 c2 = g_csr[e + 2];
            int2 c3 = g_csr[e + 3];
            uint2 u0 = *(const uint2*)(Yq + c0.x);
            uint2 u1 = *(const uint2*)(Yq + c1.x);
            uint2 u2 = *(const uint2*)(Yq + c2.x);
            uint2 u3 = *(const uint2*)(Yq + c3.x);
            float4 v0 = h4_to_f4(u0), v1 = h4_to_f4(u1);
            float4 v2 = h4_to_f4(u2), v3 = h4_to_f4(u3);
            float w0 = __int_as_float(c0.y), w1 = __int_as_float(c1.y);
            float w2 = __int_as_float(c2.y), w3 = __int_as_float(c3.y);
            a.x += w0 * v0.x + w1 * v1.x + w2 * v2.x + w3 * v3.x;
            a.y += w0 * v0.y + w1 * v1.y + w2 * v2.y + w3 * v3.y;
            a.z += w0 * v0.z + w1 * v1.z + w2 * v2.z + w3 * v3.z;
            a.w += w0 * v0.w + w1 * v1.w + w2 * v2.w + w3 * v3.w;
        }
        for (; e < end; e++) {
            int2 c0 = g_csr[e];
            uint2 u0 = *(const uint2*)(Yq + c0.x);
            float4 v0 = h4_to_f4(u0);
            float w0 = __int_as_float(c0.y);
            a.x += w0 * v0.x;  a.y += w0 * v0.y;
            a.z += w0 * v0.z;  a.w += w0 * v0.w;
        }

        float  di   = g_dinv[node];
        float4 self = h4_to_f4(*(const uint2*)(Yq + (node << 7)));
        a.x = di * (a.x + di * self.x) + b.x;
        a.y = di * (a.y + di * self.y) + b.y;
        a.z = di * (a.z + di * self.z) + b.z;
        a.w = di * (a.w + di * self.w) + b.w;
        a.x = fmaxf(a.x, 0.f) * sc.x + shf.x;
        a.y = fmaxf(a.y, 0.f) * sc.y + shf.y;
        a.z = fmaxf(a.z, 0.f) * sc.z + shf.z;
        a.w = fmaxf(a.w, 0.f) * sc.w + shf.w;

        if (RES) {
            float4 rr = ((const float4*)(RES + (size_t)node * 64))[q];
            a.x += rr.x; a.y += rr.y; a.z += rr.z; a.w += rr.w;
        }
        ((float4*)(OUT + (size_t)node * 64))[q] = a;
    }
}

// ---------------- pooling + MLP head (fused via last-block-done) -------------
__global__ void k_pool_head(const int* __restrict__ batch,
                            const float* __restrict__ hW1, const float* __restrict__ hb1,
                            const float* __restrict__ hg,  const float* __restrict__ hbeta,
                            const float* __restrict__ hm,  const float* __restrict__ hv,
                            const float* __restrict__ hW2, const float* __restrict__ hb2,
                            float* __restrict__ out) {
    const float* X5 = (const float*)g_xa;
    int c = threadIdx.x;
    int start = blockIdx.x * 512;
    if (start < N_NODES) {
        int endn = min(start + 512, N_NODES);
        float acc = 0.f;
        int run = 0;
        int gcur = batch[start];
        for (int n = start; n < endn; n++) {
            int g = batch[n];
            if (g != gcur) {
                atomicAdd(&g_ssum[gcur * 64 + c], acc);
                if (c == 0) atomicAdd(&g_cnt[gcur], (float)run);
                acc = 0.f; run = 0; gcur = g;
            }
            acc += X5[(size_t)n * 64 + c];
            run++;
        }
        atomicAdd(&g_ssum[gcur * 64 + c], acc);
        if (c == 0) atomicAdd(&g_cnt[gcur], (float)run);
    }

    __threadfence();
    __shared__ int lastf;
    if (threadIdx.x == 0) {
        int d = atomicAdd(&g_pdone, 1);
        lastf = (d == (int)gridDim.x - 1);
        if (lastf) g_pdone = 0;                   // reset for next replay
    }
    __syncthreads();
    if (!lastf) return;

    int g = threadIdx.x;                          // 64 threads = 64 graphs
    float inv = 1.f / fmaxf(g_cnt[g], 1.f);
    float gv[64];
#pragma unroll
    for (int k = 0; k < 64; k++) gv[k] = g_ssum[g * 64 + k] * inv;
    float o = hb2[0];
    for (int j = 0; j < 32; j++) {
        float s = hb1[j];
#pragma unroll
        for (int k = 0; k < 64; k++) s += gv[k] * hW1[k * 32 + j];
        s = fmaxf(s, 0.f);
        s = (s - hm[j]) * (hg[j] * rsqrtf(hv[j] + EPSV)) + hbeta[j];
        o += s * hW2[j];
    }
    out[g] = o;
}

// ---------------- launcher ---------------------------------------------------
extern "C" void kernel_launch(void* const* d_in, const int* in_sizes, int n_in,
                              void* d_out, int out_size) {
    const float* x     = (const float*)d_in[0];
    const int*   ei    = (const int*)  d_in[1];
    const int*   batch = (const int*)  d_in[2];
    const float* Wc    = (const float*)d_in[3];
    const float* bc    = (const float*)d_in[4];
    const float* bn_g  = (const float*)d_in[5];
    const float* bn_b  = (const float*)d_in[6];
    const float* bn_m  = (const float*)d_in[7];
    const float* bn_v  = (const float*)d_in[8];
    const float* hW1   = (const float*)d_in[9];
    const float* hb1   = (const float*)d_in[10];
    const float* hg    = (const float*)d_in[11];
    const float* hbe   = (const float*)d_in[12];
    const float* hm    = (const float*)d_in[13];
    const float* hv    = (const float*)d_in[14];
    const float* hW2   = (const float*)d_in[15];
    const float* hb2   = (const float*)d_in[16];
    float* out = (float*)d_out;

    const int* src = ei;
    const int* dst = ei + N_EDGES;

    // --- CSR build: 2 kernels ---
    k_count       <<<(N_EDGES + 255) / 256, 256>>>(dst);
    k_scan_scatter<<<(N_NODES + 511) / 512, 512>>>(src, dst);

    // --- 5 GCN layers ---
    const int gemm_grid = (N_NODES + 127) / 128;                // 782

    k_gemm<<<gemm_grid, 256>>>(x, -1, Wc + 0 * 4096);
    k_agg <<<AGG_GRID, 256>>>(-1, 0, bc + 0, bn_g + 0, bn_b + 0, bn_m + 0, bn_v + 0);
    k_gemm<<<gemm_grid, 256>>>(nullptr, 0, Wc + 1 * 4096);
    k_agg <<<AGG_GRID, 256>>>(0, 1, bc + 64, bn_g + 64, bn_b + 64, bn_m + 64, bn_v + 64);
    k_gemm<<<gemm_grid, 256>>>(nullptr, 1, Wc + 2 * 4096);
    k_agg <<<AGG_GRID, 256>>>(1, 0, bc + 128, bn_g + 128, bn_b + 128, bn_m + 128, bn_v + 128);
    k_gemm<<<gemm_grid, 256>>>(nullptr, 0, Wc + 3 * 4096);
    k_agg <<<AGG_GRID, 256>>>(0, 1, bc + 192, bn_g + 192, bn_b + 192, bn_m + 192, bn_v + 192);
    k_gemm<<<gemm_grid, 256>>>(nullptr, 1, Wc + 4 * 4096);
    k_agg <<<AGG_GRID, 256>>>(1, 0, bc + 256, bn_g + 256, bn_b + 256, bn_m + 256, bn_v + 256);

    // --- pool + head (fused) ---
    k_pool_head<<<(N_NODES + 511) / 512, 64>>>(batch, hW1, hb1, hg, hbe, hm, hv, hW2, hb2, out);
}

// round 14
// speedup vs baseline: 1.5005x; 1.0185x over previous
#include <cuda_runtime.h>
#include <cuda_fp16.h>

#define N_NODES 100000
#define N_EDGES 1000000
#define N_GRAPHS 64
#define HD 64
#define EPSV 1e-5f
#define AGG_GRID 1036   // 7 blocks/SM x 148 SMs, fully resident grid-stride

// ---------------- scratch (device globals; no allocation allowed) ------------
__device__ __half g_yh[N_NODES * HD];  // GEMM output (fp16, randomly gathered)
__device__ float g_xa[N_NODES * HD];   // ping (fp32 layer outputs)
__device__ float g_xb[N_NODES * HD];   // pong
__device__ int   g_deg[N_NODES];       // re-zeroed every run after use
__device__ float g_dinv[N_NODES];
__device__ int   g_rowptr[N_NODES + 1];
__device__ int   g_cursor[N_NODES];
__device__ __align__(16) int2 g_csr[N_EDGES];  // .x = src byte offset, .y = dinv bits
__device__ int   g_partial[256];       // scan lookback state (agg+1, 0=not ready)
__device__ float g_ssum[N_GRAPHS * HD];
__device__ float g_cnt[N_GRAPHS];
__device__ int   g_sync1;              // device-wide barrier arrive count
__device__ int   g_sync2;              // device-wide barrier pass count
__device__ int   g_pdone;              // pool blocks done

// ---------------- kernel 0: degree count + zero pool/scan state --------------
__global__ void k_count(const int* __restrict__ dst) {
    int e = blockIdx.x * blockDim.x + threadIdx.x;
    if (e < N_EDGES) atomicAdd(&g_deg[dst[e]], 1);
    if (e < N_GRAPHS * HD) g_ssum[e] = 0.f;
    if (e < N_GRAPHS)      g_cnt[e]  = 0.f;
    if (e < 256)           g_partial[e] = 0;
}

// ---------------- kernel 1: scan + dinv + device barrier + scatter -----------
__global__ void __launch_bounds__(512) k_scan_scatter(const int* __restrict__ src,
                                                      const int* __restrict__ dst) {
    __shared__ int sh[512];
    __shared__ int shp[256];
    int tid = threadIdx.x;
    int bid = blockIdx.x;
    int i = bid * 512 + tid;

    int v = (i < N_NODES) ? g_deg[i] : 0;
    if (i < N_NODES) {
        g_dinv[i] = rsqrtf((float)(v + 1));
        g_deg[i]  = 0;                           // re-zero for next replay
    }

    sh[tid] = v;
    __syncthreads();
    for (int off = 1; off < 512; off <<= 1) {
        int t = (tid >= off) ? sh[tid - off] : 0;
        __syncthreads();
        sh[tid] += t;
        __syncthreads();
    }
    int incl  = sh[tid];
    int total = sh[511];

    if (tid == 0) {                               // publish aggregate
        __threadfence();
        atomicExch(&g_partial[bid], total + 1);
    }

    if (tid < 256) {                              // parallel spin on predecessors
        int p = 0;
        if (tid < bid) {
            do { p = atomicAdd(&g_partial[tid], 0); } while (p == 0);
            p -= 1;
        }
        shp[tid] = p;
    }
    __syncthreads();
    for (int off = 128; off > 0; off >>= 1) {
        if (tid < off) shp[tid] += shp[tid + off];
        __syncthreads();
    }
    int offset = shp[0];

    if (i < N_NODES) {
        int ex = offset + incl - v;
        g_rowptr[i] = ex;
        g_cursor[i] = ex;
    }
    if (bid == 0 && tid == 0) g_rowptr[N_NODES] = N_EDGES;

    // ---- device-wide barrier (self-resetting) ----
    __threadfence();
    __syncthreads();
    if (tid == 0) {
        atomicAdd(&g_sync1, 1);
        while (atomicAdd(&g_sync1, 0) < (int)gridDim.x) {}
        int p = atomicAdd(&g_sync2, 1);
        if (p == (int)gridDim.x - 1) {            // last to pass: everyone is out
            g_sync1 = 0;
            g_sync2 = 0;
            __threadfence();
        }
    }
    __syncthreads();

    // ---- phase 2: scatter edges into CSR (payload = byte offset of src row) --
    int stride = gridDim.x * 512;
    for (int e = i; e < N_EDGES; e += stride) {
        int d = dst[e];
        int s = src[e];
        int p = atomicAdd(&g_cursor[d], 1);
        g_csr[p] = make_int2(s << 7, __float_as_int(g_dinv[s]));
    }
}

// ---------------- GEMM v4: outer-product f32x2, vectorized LDS ---------------
// Per k: 2 LDS.128 (x row-pairs, compile-time permute) + 1 LDS.128 (w float4)
// + 4 pair-packs -> 16 FFMA2.
__global__ void __launch_bounds__(256) k_gemm(const float* __restrict__ Xext, int xsel,
                                              const float* __restrict__ W) {
    __shared__ float xs[64 * 128];   // 32KB: [k][2*rp + b], swizzled
    __shared__ float wt[64 * 64];    // 16KB: W copy, row-major [k][c]
    const float* X = (xsel < 0) ? Xext : (xsel == 0 ? (const float*)g_xa : (const float*)g_xb);

    int tid  = threadIdx.x;
    int lane = tid & 31;
    int wid  = tid >> 5;          // 0..7
    int cg   = lane & 15;         // col group: cols cg*4 .. cg*4+3
    int rh   = lane >> 4;         // 0/1
    int rg   = wid * 2 + rh;      // 0..15 -> rows rg*8 .. rg*8+7
    int rp0  = rg * 4;            // first row-pair (aligned to 4)

#pragma unroll
    for (int it = 0; it < 16; it++) wt[it * 256 + tid] = W[it * 256 + tid];

    int rt = blockIdx.x * 128;
#pragma unroll
    for (int it = 0; it < 8; it++) {
        int idx = it * 256 + tid;
        int cq  = idx & 15;
        int row = idx >> 4;
        int grow = rt + row;
        float4 x4 = make_float4(0.f, 0.f, 0.f, 0.f);
        if (grow < N_NODES) x4 = *(const float4*)&X[(size_t)grow * 64 + 4 * cq];
        int u  = row >> 1;
        int rb = row & 1;
        float vals[4] = {x4.x, x4.y, x4.z, x4.w};
#pragma unroll
        for (int m = 0; m < 4; m++) {
            int K  = 4 * cq + m;
            int gk = (K + (K >> 2)) & 15;
            xs[K * 128 + 2 * (u ^ gk) + rb] = vals[m];
        }
    }
    __syncthreads();

    // 4 precomputed x bases for gk&~3 in {0,4,8,12}; each 32B-aligned (rp0%4==0)
    const float* xb0 = &xs[2 * (rp0 ^ 0)];
    const float* xb1 = &xs[2 * (rp0 ^ 4)];
    const float* xb2 = &xs[2 * (rp0 ^ 8)];
    const float* xb3 = &xs[2 * (rp0 ^ 12)];
    const float* wb  = &wt[cg * 4];

    unsigned long long acc[4][4];
#pragma unroll
    for (int j = 0; j < 4; j++)
#pragma unroll
        for (int cc = 0; cc < 4; cc++) acc[j][cc] = 0ULL;

#pragma unroll
    for (int k = 0; k < 64; k++) {
        const int gk  = (k + (k >> 2)) & 15;
        const int ghi = gk >> 2;
        const int glo = gk & 3;
        const float* xbase = (ghi == 0) ? xb0 : (ghi == 1) ? xb1 : (ghi == 2) ? xb2 : xb3;

        // the 4 row-pair u64s always occupy 32 contiguous bytes; XOR only permutes
        ulonglong2 xa  = *(const ulonglong2*)(xbase + k * 128);
        ulonglong2 xbv = *(const ulonglong2*)(xbase + k * 128 + 4);
        unsigned long long p[4] = {xa.x, xa.y, xbv.x, xbv.y};

        float4 wv = *(const float4*)&wb[k * 64];
        unsigned long long wd[4];
        asm("mov.b64 %0, {%1, %1};" : "=l"(wd[0]) : "f"(wv.x));
        asm("mov.b64 %0, {%1, %1};" : "=l"(wd[1]) : "f"(wv.y));
        asm("mov.b64 %0, {%1, %1};" : "=l"(wd[2]) : "f"(wv.z));
        asm("mov.b64 %0, {%1, %1};" : "=l"(wd[3]) : "f"(wv.w));

#pragma unroll
        for (int j = 0; j < 4; j++)
#pragma unroll
            for (int cc = 0; cc < 4; cc++)
                asm("fma.rn.f32x2 %0, %1, %2, %0;"
                    : "+l"(acc[j][cc]) : "l"(p[j ^ glo]), "l"(wd[cc]));
    }

#pragma unroll
    for (int j = 0; j < 4; j++) {
        int row = rt + rg * 8 + 2 * j;
        float lo0, hi0, lo1, hi1, lo2, hi2, lo3, hi3;
        asm("mov.b64 {%0,%1}, %2;" : "=f"(lo0), "=f"(hi0) : "l"(acc[j][0]));
        asm("mov.b64 {%0,%1}, %2;" : "=f"(lo1), "=f"(hi1) : "l"(acc[j][1]));
        asm("mov.b64 {%0,%1}, %2;" : "=f"(lo2), "=f"(hi2) : "l"(acc[j][2]));
        asm("mov.b64 {%0,%1}, %2;" : "=f"(lo3), "=f"(hi3) : "l"(acc[j][3]));
        if (row < N_NODES) {
            __half2* p = (__half2*)&g_yh[(size_t)row * 64 + cg * 4];
            p[0] = __floats2half2_rn(lo0, lo1);
            p[1] = __floats2half2_rn(lo2, lo3);
        }
        if (row + 1 < N_NODES) {
            __half2* p = (__half2*)&g_yh[(size_t)(row + 1) * 64 + cg * 4];
            p[0] = __floats2half2_rn(hi0, hi1);
            p[1] = __floats2half2_rn(hi2, hi3);
        }
    }
}

// ---------------- fused aggregation + bias + ReLU + BN + residual ------------
// v3: int4 CSR loads (2 edges per LDG.128, parity peel), byte-offset gathers,
// fully-resident grid-stride, folded BN epilogue.
__device__ __forceinline__ float4 h4_to_f4(uint2 u) {
    float2 lo = __half22float2(*(__half2*)&u.x);
    float2 hi = __half22float2(*(__half2*)&u.y);
    return make_float4(lo.x, lo.y, hi.x, hi.y);
}

__global__ void __launch_bounds__(256, 7) k_agg(int res_sel, int out_sel,
                                                const float* __restrict__ bias,
                                                const float* __restrict__ gamma,
                                                const float* __restrict__ beta,
                                                const float* __restrict__ mean,
                                                const float* __restrict__ var) {
    int lane = threadIdx.x & 31;
    int q    = lane & 15;
    int half = lane >> 4;
    int w0i  = (blockIdx.x * 256 + threadIdx.x) >> 5;
    const int NW = AGG_GRID * 8;        // warps in grid
    const int NPAIR = N_NODES / 2;

    const char*   Yq  = (const char*)g_yh + q * 8;   // lane's 8-byte slot
    float*        OUT = out_sel ? g_xb : g_xa;
    const float*  RES = (res_sel < 0) ? nullptr
                                      : (res_sel == 0 ? (const float*)g_xa : (const float*)g_xb);

    // per-thread invariant epilogue params (folded BN)
    float4 b  = ((const float4*)bias)[q];
    float4 ga = ((const float4*)gamma)[q];
    float4 be = ((const float4*)beta)[q];
    float4 mm = ((const float4*)mean)[q];
    float4 vv = ((const float4*)var)[q];
    float4 sc;
    sc.x = ga.x * rsqrtf(vv.x + EPSV);
    sc.y = ga.y * rsqrtf(vv.y + EPSV);
    sc.z = ga.z * rsqrtf(vv.z + EPSV);
    sc.w = ga.w * rsqrtf(vv.w + EPSV);
    float4 shf;
    shf.x = be.x - mm.x * sc.x;
    shf.y = be.y - mm.y * sc.y;
    shf.z = be.z - mm.z * sc.z;
    shf.w = be.w - mm.w * sc.w;

    for (int gw = w0i; gw < NPAIR; gw += NW) {
        int node = gw * 2 + half;

        int beg = g_rowptr[node], end = g_rowptr[node + 1];
        float4 a = make_float4(0.f, 0.f, 0.f, 0.f);

        int e = beg;
        // parity peel: align e to even (16B) for int4 CSR loads
        if ((e & 1) && e < end) {
            int2 c0 = g_csr[e];
            uint2 u0 = *(const uint2*)(Yq + c0.x);
            float4 v0 = h4_to_f4(u0);
            float w0 = __int_as_float(c0.y);
            a.x += w0 * v0.x;  a.y += w0 * v0.y;
            a.z += w0 * v0.z;  a.w += w0 * v0.w;
            e++;
        }
        for (; e + 3 < end; e += 4) {
            int4 cA = *(const int4*)&g_csr[e];       // edges e, e+1
            int4 cB = *(const int4*)&g_csr[e + 2];   // edges e+2, e+3
            uint2 u0 = *(const uint2*)(Yq + cA.x);
            uint2 u1 = *(const uint2*)(Yq + cA.z);
            uint2 u2 = *(const uint2*)(Yq + cB.x);
            uint2 u3 = *(const uint2*)(Yq + cB.z);
            float4 v0 = h4_to_f4(u0), v1 = h4_to_f4(u1);
            float4 v2 = h4_to_f4(u2), v3 = h4_to_f4(u3);
            float w0 = __int_as_float(cA.y), w1 = __int_as_float(cA.w);
            float w2 = __int_as_float(cB.y), w3 = __int_as_float(cB.w);
            a.x += w0 * v0.x + w1 * v1.x + w2 * v2.x + w3 * v3.x;
            a.y += w0 * v0.y + w1 * v1.y + w2 * v2.y + w3 * v3.y;
            a.z += w0 * v0.z + w1 * v1.z + w2 * v2.z + w3 * v3.z;
            a.w += w0 * v0.w + w1 * v1.w + w2 * v2.w + w3 * v3.w;
        }
        if (e + 1 < end) {                           // 2-edge step (e still even)
            int4 cA = *(const int4*)&g_csr[e];
            uint2 u0 = *(const uint2*)(Yq + cA.x);
            uint2 u1 = *(const uint2*)(Yq + cA.z);
            float4 v0 = h4_to_f4(u0), v1 = h4_to_f4(u1);
            float w0 = __int_as_float(cA.y), w1 = __int_as_float(cA.w);
            a.x += w0 * v0.x + w1 * v1.x;
            a.y += w0 * v0.y + w1 * v1.y;
            a.z += w0 * v0.z + w1 * v1.z;
            a.w += w0 * v0.w + w1 * v1.w;
            e += 2;
        }
        if (e < end) {                               // final single
            int2 c0 = g_csr[e];
            uint2 u0 = *(const uint2*)(Yq + c0.x);
            float4 v0 = h4_to_f4(u0);
            float w0 = __int_as_float(c0.y);
            a.x += w0 * v0.x;  a.y += w0 * v0.y;
            a.z += w0 * v0.z;  a.w += w0 * v0.w;
        }

        float  di   = g_dinv[node];
        float4 self = h4_to_f4(*(const uint2*)(Yq + (node << 7)));
        a.x = di * (a.x + di * self.x) + b.x;
        a.y = di * (a.y + di * self.y) + b.y;
        a.z = di * (a.z + di * self.z) + b.z;
        a.w = di * (a.w + di * self.w) + b.w;
        a.x = fmaxf(a.x, 0.f) * sc.x + shf.x;
        a.y = fmaxf(a.y, 0.f) * sc.y + shf.y;
        a.z = fmaxf(a.z, 0.f) * sc.z + shf.z;
        a.w = fmaxf(a.w, 0.f) * sc.w + shf.w;

        if (RES) {
            float4 rr = ((const float4*)(RES + (size_t)node * 64))[q];
            a.x += rr.x; a.y += rr.y; a.z += rr.z; a.w += rr.w;
        }
        ((float4*)(OUT + (size_t)node * 64))[q] = a;
    }
}

// ---------------- pooling + MLP head (fused via last-block-done) -------------
__global__ void k_pool_head(const int* __restrict__ batch,
                            const float* __restrict__ hW1, const float* __restrict__ hb1,
                            const float* __restrict__ hg,  const float* __restrict__ hbeta,
                            const float* __restrict__ hm,  const float* __restrict__ hv,
                            const float* __restrict__ hW2, const float* __restrict__ hb2,
                            float* __restrict__ out) {
    const float* X5 = (const float*)g_xa;
    int c = threadIdx.x;
    int start = blockIdx.x * 512;
    if (start < N_NODES) {
        int endn = min(start + 512, N_NODES);
        float acc = 0.f;
        int run = 0;
        int gcur = batch[start];
        for (int n = start; n < endn; n++) {
            int g = batch[n];
            if (g != gcur) {
                atomicAdd(&g_ssum[gcur * 64 + c], acc);
                if (c == 0) atomicAdd(&g_cnt[gcur], (float)run);
                acc = 0.f; run = 0; gcur = g;
            }
            acc += X5[(size_t)n * 64 + c];
            run++;
        }
        atomicAdd(&g_ssum[gcur * 64 + c], acc);
        if (c == 0) atomicAdd(&g_cnt[gcur], (float)run);
    }

    __threadfence();
    __shared__ int lastf;
    if (threadIdx.x == 0) {
        int d = atomicAdd(&g_pdone, 1);
        lastf = (d == (int)gridDim.x - 1);
        if (lastf) g_pdone = 0;                   // reset for next replay
    }
    __syncthreads();
    if (!lastf) return;

    int g = threadIdx.x;                          // 64 threads = 64 graphs
    float inv = 1.f / fmaxf(g_cnt[g], 1.f);
    float gv[64];
#pragma unroll
    for (int k = 0; k < 64; k++) gv[k] = g_ssum[g * 64 + k] * inv;
    float o = hb2[0];
    for (int j = 0; j < 32; j++) {
        float s = hb1[j];
#pragma unroll
        for (int k = 0; k < 64; k++) s += gv[k] * hW1[k * 32 + j];
        s = fmaxf(s, 0.f);
        s = (s - hm[j]) * (hg[j] * rsqrtf(hv[j] + EPSV)) + hbeta[j];
        o += s * hW2[j];
    }
    out[g] = o;
}

// ---------------- launcher ---------------------------------------------------
extern "C" void kernel_launch(void* const* d_in, const int* in_sizes, int n_in,
                              void* d_out, int out_size) {
    const float* x     = (const float*)d_in[0];
    const int*   ei    = (const int*)  d_in[1];
    const int*   batch = (const int*)  d_in[2];
    const float* Wc    = (const float*)d_in[3];
    const float* bc    = (const float*)d_in[4];
    const float* bn_g  = (const float*)d_in[5];
    const float* bn_b  = (const float*)d_in[6];
    const float* bn_m  = (const float*)d_in[7];
    const float* bn_v  = (const float*)d_in[8];
    const float* hW1   = (const float*)d_in[9];
    const float* hb1   = (const float*)d_in[10];
    const float* hg    = (const float*)d_in[11];
    const float* hbe   = (const float*)d_in[12];
    const float* hm    = (const float*)d_in[13];
    const float* hv    = (const float*)d_in[14];
    const float* hW2   = (const float*)d_in[15];
    const float* hb2   = (const float*)d_in[16];
    float* out = (float*)d_out;

    const int* src = ei;
    const int* dst = ei + N_EDGES;

    // --- CSR build: 2 kernels ---
    k_count       <<<(N_EDGES + 255) / 256, 256>>>(dst);
    k_scan_scatter<<<(N_NODES + 511) / 512, 512>>>(src, dst);

    // --- 5 GCN layers ---
    const int gemm_grid = (N_NODES + 127) / 128;                // 782

    k_gemm<<<gemm_grid, 256>>>(x, -1, Wc + 0 * 4096);
    k_agg <<<AGG_GRID, 256>>>(-1, 0, bc + 0, bn_g + 0, bn_b + 0, bn_m + 0, bn_v + 0);
    k_gemm<<<gemm_grid, 256>>>(nullptr, 0, Wc + 1 * 4096);
    k_agg <<<AGG_GRID, 256>>>(0, 1, bc + 64, bn_g + 64, bn_b + 64, bn_m + 64, bn_v + 64);
    k_gemm<<<gemm_grid, 256>>>(nullptr, 1, Wc + 2 * 4096);
    k_agg <<<AGG_GRID, 256>>>(1, 0, bc + 128, bn_g + 128, bn_b + 128, bn_m + 128, bn_v + 128);
    k_gemm<<<gemm_grid, 256>>>(nullptr, 0, Wc + 3 * 4096);
    k_agg <<<AGG_GRID, 256>>>(0, 1, bc + 192, bn_g + 192, bn_b + 192, bn_m + 192, bn_v + 192);
    k_gemm<<<gemm_grid, 256>>>(nullptr, 1, Wc + 4 * 4096);
    k_agg <<<AGG_GRID, 256>>>(1, 0, bc + 256, bn_g + 256, bn_b + 256, bn_m + 256, bn_v + 256);

    // --- pool + head (fused) ---
    k_pool_head<<<(N_NODES + 511) / 512, 64>>>(batch, hW1, hb1, hg, hbe, hm, hv, hW2, hb2, out);
}